// round 14
// baseline (speedup 1.0000x reference)
#include <cuda_runtime.h>
#include <cuda_bf16.h>

#define NN 16384      // nodes/edges (and bond_n rows A = 16384)
#define DD 128        // emb dim
// Only layer i = 2 matters: the reference loop does not feed h back.

// Scratch (device globals — zero-initialized at module load)
__device__ float g_hn[(size_t)NN * DD];      // 8 MB
__device__ float g_mpartT[DD][128];          // m partials, contiguous per d (64 KB)
__device__ unsigned g_hflag[128];            // h_n-ready flags (k_out resets)

// ---------------------------------------------------------------------------
// k_fused, 256 blocks (all co-resident @ 2/SM -> pairwise flag is safe):
//   blocks [128,256): GEMM h_n = relu(cat @ Wi_w[2].T + b) -> g_hn,
//                     then set g_hflag[bid-128] (done at ~25us).
//   blocks [0,128):   column-sum of bond_n cols [bid*128,+128) over all rows
//                     (colw stays in SMEM; no global colw at all), then poll
//                     g_hflag[bid] (set 150us earlier -> free), read the
//                     matching 128 h_n rows, m-partial -> g_mpartT[d][bid].
// No atomics on data; fully deterministic.
// ---------------------------------------------------------------------------
__global__ void __launch_bounds__(256) k_fused(
    const float* __restrict__ bn,
    const int* __restrict__ x, const int* __restrict__ ea,
    const float* __restrict__ aemb, const float* __restrict__ bemb,
    const float* __restrict__ Wi_w2, const float* __restrict__ Wi_b2)
{
    extern __shared__ float sm[];
    const int tid = threadIdx.x;
    const int bid = blockIdx.x;

    if (bid < 128) {
        // ---------------- column-sum path ----------------
        __shared__ float colw_s[128];
        __shared__ float red[256];
        const int lane = tid & 31, warp = tid >> 5;
        // each thread: 4 columns, rows warp, warp+8, ... (2048 rows)
        const float* base = bn + (size_t)warp * NN + bid * 128 + lane * 4;
        float4 a0 = {0,0,0,0}, a1 = {0,0,0,0}, a2 = {0,0,0,0}, a3 = {0,0,0,0};
        for (int i = 0; i < 2048; i += 16) {
#pragma unroll
            for (int u = 0; u < 16; u++) {
                float4 v = __ldcs((const float4*)(base + (size_t)(i + u) * 8 * NN));
                float4& a = (u & 3) == 0 ? a0 : (u & 3) == 1 ? a1 : (u & 3) == 2 ? a2 : a3;
                a.x += v.x; a.y += v.y; a.z += v.z; a.w += v.w;
            }
        }
        float sx = a0.x + a1.x + a2.x + a3.x;
        float sy = a0.y + a1.y + a2.y + a3.y;
        float sz = a0.z + a1.z + a2.z + a3.z;
        float sw = a0.w + a1.w + a2.w + a3.w;
        // cross-warp reduce: part[8][128] in dynamic smem
        float* part = sm;
        part[warp * 128 + lane * 4 + 0] = sx;
        part[warp * 128 + lane * 4 + 1] = sy;
        part[warp * 128 + lane * 4 + 2] = sz;
        part[warp * 128 + lane * 4 + 3] = sw;
        __syncthreads();
        if (tid < 128) {
            float s = 0.f;
#pragma unroll
            for (int w = 0; w < 8; w++) s += part[w * 128 + tid];
            colw_s[tid] = s;
        }
        __syncthreads();

        // wait for partner GEMM block's h_n (set ~150us ago -> instant)
        if (tid == 0) {
            volatile unsigned* f = &g_hflag[bid];
            while (*f == 0u) __nanosleep(64);
        }
        __syncthreads();
        __threadfence();

        // m-partial over h_n rows [bid*128, +128): p[d] = sum_r colw[r]*hn[r,d]
        {
            const float* hn = g_hn + (size_t)bid * 128 * 128;
            const int d = tid & 127, half = tid >> 7;
            float p = 0.f;
#pragma unroll 16
            for (int r = 0; r < 64; r++) {
                int row = half * 64 + r;
                p = fmaf(colw_s[row], __ldcg(&hn[row * 128 + d]), p);
            }
            red[tid] = p;
        }
        __syncthreads();
        if (tid < 128) g_mpartT[tid][bid] = red[tid] + red[tid + 128];
        return;
    }

    // ---------------- GEMM path ----------------
    float* w_s   = sm;                 // [64][129]  = 33,024 B (per-k chunk)
    float* cat_s = sm + 64 * 129;      // [128][64]  = 32,768 B

    __shared__ float bias_s[128];
    __shared__ int xi0[128], xi1[128], ei0[128], ei1[128];

    const int rowBase = (bid - 128) * 128;

    if (tid < 128) {
        bias_s[tid] = Wi_b2[tid];
        int r = rowBase + tid;
        xi0[tid] = x[2 * r];  xi1[tid] = x[2 * r + 1];
        ei0[tid] = ea[2 * r]; ei1[tid] = ea[2 * r + 1];
    }
    __syncthreads();

    const int tx = tid & 15, ty = tid >> 4;
    float acc[8][8];
#pragma unroll
    for (int i = 0; i < 8; i++)
#pragma unroll
        for (int j = 0; j < 8; j++) acc[i][j] = 0.f;

    for (int kc = 0; kc < 256; kc += 64) {
        // stage W chunk transposed: w_s[kk][d] = Wi_w2[d*256 + kc + kk]
        for (int idx = tid; idx < 8192; idx += 256) {
            int d = idx >> 6, kk = idx & 63;
            w_s[kk * 129 + d] = Wi_w2[d * 256 + kc + kk];
        }
        // stage cat chunk: cat_s[row][kloc] (embedding pair-sum gathers)
        const bool atom = (kc < 128);
        const float* emb = atom ? aemb : bemb;
        for (int idx = tid; idx < 2048; idx += 256) {
            int row  = idx >> 4;
            int kloc = (idx & 15) * 4;
            int i0 = atom ? xi0[row] : ei0[row];
            int i1 = atom ? xi1[row] : ei1[row];
            int ko = atom ? (kc + kloc) : (kc - 128 + kloc);
            float4 v0 = *(const float4*)(emb + i0 * 128 + ko);
            float4 v1 = *(const float4*)(emb + i1 * 128 + ko);
            float4 s;
            s.x = v0.x + v1.x; s.y = v0.y + v1.y;
            s.z = v0.z + v1.z; s.w = v0.w + v1.w;
            *(float4*)(cat_s + row * 64 + kloc) = s;
        }
        __syncthreads();

#pragma unroll 8
        for (int kk = 0; kk < 64; kk++) {
            const float* wr = w_s + kk * 129;
            float b[8], a[8];
#pragma unroll
            for (int j = 0; j < 8; j++) b[j] = wr[tx + 16 * j];
#pragma unroll
            for (int i = 0; i < 8; i++) a[i] = cat_s[(ty + 16 * i) * 64 + kk];
#pragma unroll
            for (int i = 0; i < 8; i++)
#pragma unroll
                for (int j = 0; j < 8; j++)
                    acc[i][j] = fmaf(a[i], b[j], acc[i][j]);
        }
        __syncthreads();
    }

    // epilogue: bias + relu -> g_hn, then release flag
#pragma unroll
    for (int i = 0; i < 8; i++) {
        int r = ty + 16 * i;
#pragma unroll
        for (int j = 0; j < 8; j++) {
            int d = tx + 16 * j;
            float v = acc[i][j] + bias_s[d];
            g_hn[(size_t)(rowBase + r) * 128 + d] = v > 0.f ? v : 0.f;
        }
    }
    __threadfence();                    // every thread: release its h_n stores
    __syncthreads();
    if (tid == 0) *((volatile unsigned*)&g_hflag[bid - 128]) = 1u;
}

// ---------------------------------------------------------------------------
// k_out, 256 blocks x 256 threads (64 h_n rows each):
//   per block (redundant, L2-hot): m[d] = sum of 128 contiguous partials,
//   mm = m @ Wm^T + b; then out = relu(h_n + mm) for own rows.
//   Block 0 resets g_hflag for the next graph replay.
// ---------------------------------------------------------------------------
__global__ void __launch_bounds__(256) k_out(const float* __restrict__ Wm_w2,
                                             const float* __restrict__ Wm_b2,
                                             float* __restrict__ out) {
    __shared__ float red[256];
    __shared__ float ms[128];
    __shared__ float mm_s[128];

    const int bid = blockIdx.x, tid = threadIdx.x;
    const int d = tid & 127, half = tid >> 7;

    if (bid == 0 && tid < 128) g_hflag[tid] = 0u;   // reset for next replay

    // m reduce: per d, 128 partials = 32 contiguous float4; halves split 16+16
    {
        const float4* mp = (const float4*)g_mpartT[d] + half * 16;
        float s = 0.f;
#pragma unroll 16
        for (int w = 0; w < 16; w++) {
            float4 v = __ldcg(mp + w);
            s += v.x + v.y + v.z + v.w;
        }
        red[tid] = s;
    }
    __syncthreads();
    if (tid < 128) ms[tid] = red[tid] + red[tid + 128];
    __syncthreads();

    if (tid < 128) {
        float s = Wm_b2[tid];
        const float* row = Wm_w2 + tid * 128;
#pragma unroll 8
        for (int k = 0; k < 128; k++) s = fmaf(ms[k], __ldg(row + k), s);
        mm_s[tid] = s;
    }
    __syncthreads();

    // out = relu(h_n + mm) for rows [bid*64, +64): 2048 float4
    {
        const float* hn = g_hn + (size_t)bid * 64 * 128;
        float4* ob = (float4*)(out + (size_t)bid * 64 * 128);
#pragma unroll 4
        for (int i = tid; i < 2048; i += 256) {
            int row = i >> 5, dg = (i & 31) * 4;
            float4 v = *(const float4*)(hn + row * 128 + dg);
            v.x = fmaxf(v.x + mm_s[dg + 0], 0.f);
            v.y = fmaxf(v.y + mm_s[dg + 1], 0.f);
            v.z = fmaxf(v.z + mm_s[dg + 2], 0.f);
            v.w = fmaxf(v.w + mm_s[dg + 3], 0.f);
            ob[i] = v;
        }
    }
}

// ---------------------------------------------------------------------------
extern "C" void kernel_launch(void* const* d_in, const int* in_sizes, int n_in,
                              void* d_out, int out_size) {
    const int*   x    = (const int*)d_in[0];
    const int*   ea   = (const int*)d_in[1];
    const float* bn   = (const float*)d_in[2];
    const float* aemb = (const float*)d_in[3];
    const float* bemb = (const float*)d_in[4];
    const float* Wi_w = (const float*)d_in[5];
    const float* Wi_b = (const float*)d_in[6];
    const float* Wm_w = (const float*)d_in[7];
    const float* Wm_b = (const float*)d_in[8];

    // Only the last layer (i = 2) affects the output.
    const float* Wi_w2 = Wi_w + 2 * 128 * 256;
    const float* Wi_b2 = Wi_b + 2 * 128;
    const float* Wm_w2 = Wm_w + 2 * 128 * 128;
    const float* Wm_b2 = Wm_b + 2 * 128;

    const int smem = (64 * 129 + 128 * 64) * (int)sizeof(float);  // 65,792 B
    static bool attr_set = false;
    if (!attr_set) {
        cudaFuncSetAttribute(k_fused, cudaFuncAttributeMaxDynamicSharedMemorySize, smem);
        attr_set = true;
    }

    k_fused<<<256, 256, smem>>>(bn, x, ea, aemb, bemb, Wi_w2, Wi_b2);
    k_out<<<256, 256>>>(Wm_w2, Wm_b2, (float*)d_out);
}

// round 15
// speedup vs baseline: 1.0355x; 1.0355x over previous
#include <cuda_runtime.h>
#include <cuda_bf16.h>

#define NN 16384      // nodes/edges (and bond_n rows A = 16384)
#define DD 128        // emb dim
// Only layer i = 2 matters: the reference loop does not feed h back.

// Scratch (device globals — zero-initialized at module load)
__device__ float g_colw[NN];
__device__ float g_hn[(size_t)NN * DD];      // 8 MB
__device__ float g_mpartT[DD][256];          // m partials, contiguous per d
__device__ float g_mm[DD];
__device__ unsigned g_cnt, g_flag, g_done;   // k_tail sync (self-resetting)

// ---------------------------------------------------------------------------
// k_fused (R13 verbatim — proven best stream): 256 blocks.
//   blocks [0,128):   column-sum of bond_n. Block b owns columns
//                     [b*128, b*128+128) over ALL 16384 rows -> g_colw.
//   blocks [128,256): GEMM h_n = relu(cat @ Wi_w[2].T + b), 128 rows each.
// ---------------------------------------------------------------------------
__global__ void __launch_bounds__(256) k_fused(
    const float* __restrict__ bn,
    const int* __restrict__ x, const int* __restrict__ ea,
    const float* __restrict__ aemb, const float* __restrict__ bemb,
    const float* __restrict__ Wi_w2, const float* __restrict__ Wi_b2)
{
    extern __shared__ float sm[];
    const int tid = threadIdx.x;
    const int bid = blockIdx.x;

    if (bid < 128) {
        // ---------------- column-sum path ----------------
        const int lane = tid & 31, warp = tid >> 5;
        const float* base = bn + (size_t)warp * NN + bid * 128 + lane * 4;
        float4 a0 = {0,0,0,0}, a1 = {0,0,0,0}, a2 = {0,0,0,0}, a3 = {0,0,0,0};
        for (int i = 0; i < 2048; i += 16) {
#pragma unroll
            for (int u = 0; u < 16; u++) {
                float4 v = __ldcs((const float4*)(base + (size_t)(i + u) * 8 * NN));
                float4& a = (u & 3) == 0 ? a0 : (u & 3) == 1 ? a1 : (u & 3) == 2 ? a2 : a3;
                a.x += v.x; a.y += v.y; a.z += v.z; a.w += v.w;
            }
        }
        float sx = a0.x + a1.x + a2.x + a3.x;
        float sy = a0.y + a1.y + a2.y + a3.y;
        float sz = a0.z + a1.z + a2.z + a3.z;
        float sw = a0.w + a1.w + a2.w + a3.w;
        float* part = sm;
        part[warp * 128 + lane * 4 + 0] = sx;
        part[warp * 128 + lane * 4 + 1] = sy;
        part[warp * 128 + lane * 4 + 2] = sz;
        part[warp * 128 + lane * 4 + 3] = sw;
        __syncthreads();
        if (tid < 128) {
            float s = 0.f;
#pragma unroll
            for (int w = 0; w < 8; w++) s += part[w * 128 + tid];
            g_colw[bid * 128 + tid] = s;
        }
        return;
    }

    // ---------------- GEMM path ----------------
    float* w_s   = sm;                 // [64][129]  = 33,024 B (per-k chunk)
    float* cat_s = sm + 64 * 129;      // [128][64]  = 32,768 B

    __shared__ float bias_s[128];
    __shared__ int xi0[128], xi1[128], ei0[128], ei1[128];

    const int rowBase = (bid - 128) * 128;

    if (tid < 128) {
        bias_s[tid] = Wi_b2[tid];
        int r = rowBase + tid;
        xi0[tid] = x[2 * r];  xi1[tid] = x[2 * r + 1];
        ei0[tid] = ea[2 * r]; ei1[tid] = ea[2 * r + 1];
    }
    __syncthreads();

    const int tx = tid & 15, ty = tid >> 4;
    float acc[8][8];
#pragma unroll
    for (int i = 0; i < 8; i++)
#pragma unroll
        for (int j = 0; j < 8; j++) acc[i][j] = 0.f;

    for (int kc = 0; kc < 256; kc += 64) {
        for (int idx = tid; idx < 8192; idx += 256) {
            int d = idx >> 6, kk = idx & 63;
            w_s[kk * 129 + d] = Wi_w2[d * 256 + kc + kk];
        }
        const bool atom = (kc < 128);
        const float* emb = atom ? aemb : bemb;
        for (int idx = tid; idx < 2048; idx += 256) {
            int row  = idx >> 4;
            int kloc = (idx & 15) * 4;
            int i0 = atom ? xi0[row] : ei0[row];
            int i1 = atom ? xi1[row] : ei1[row];
            int ko = atom ? (kc + kloc) : (kc - 128 + kloc);
            float4 v0 = *(const float4*)(emb + i0 * 128 + ko);
            float4 v1 = *(const float4*)(emb + i1 * 128 + ko);
            float4 s;
            s.x = v0.x + v1.x; s.y = v0.y + v1.y;
            s.z = v0.z + v1.z; s.w = v0.w + v1.w;
            *(float4*)(cat_s + row * 64 + kloc) = s;
        }
        __syncthreads();

#pragma unroll 8
        for (int kk = 0; kk < 64; kk++) {
            const float* wr = w_s + kk * 129;
            float b[8], a[8];
#pragma unroll
            for (int j = 0; j < 8; j++) b[j] = wr[tx + 16 * j];
#pragma unroll
            for (int i = 0; i < 8; i++) a[i] = cat_s[(ty + 16 * i) * 64 + kk];
#pragma unroll
            for (int i = 0; i < 8; i++)
#pragma unroll
                for (int j = 0; j < 8; j++)
                    acc[i][j] = fmaf(a[i], b[j], acc[i][j]);
        }
        __syncthreads();
    }

    // epilogue: bias + relu -> g_hn
#pragma unroll
    for (int i = 0; i < 8; i++) {
        int r = ty + 16 * i;
#pragma unroll
        for (int j = 0; j < 8; j++) {
            int d = tx + 16 * j;
            float v = acc[i][j] + bias_s[d];
            g_hn[(size_t)(rowBase + r) * 128 + d] = v > 0.f ? v : 0.f;
        }
    }
}

// ---------------------------------------------------------------------------
// k_tail, 256 blocks x 256 threads, __launch_bounds__(256,2) -> all
// co-resident (296 slots >= 256): ONE kernel for m + mm + epilogue.
//   1) block b: read h_n rows [b*64,+64) ONCE into registers (8 float4/thr,
//      coalesced), m-partial -> g_mpartT[d][b] (transposed).
//   2) last-arriving block alone: m reduce (64 contiguous float4 per d) +
//      mm = m @ Wm^T + b -> g_mm, release g_flag.
//   3) all blocks: wait flag (short), out = relu(h_reg + mm) from registers.
// Counters/flag self-reset via done-counter for graph replay. No data atomics.
// ---------------------------------------------------------------------------
__global__ void __launch_bounds__(256, 2) k_tail(
    const float* __restrict__ Wm_w2, const float* __restrict__ Wm_b2,
    float* __restrict__ out)
{
    __shared__ float part[8][128];
    __shared__ float colw_s[64];
    __shared__ float ms[128];
    __shared__ float mm_s[128];
    __shared__ bool last;

    const int b = blockIdx.x, tid = threadIdx.x;
    const int warp = tid >> 5;           // row group (8 rows each)
    const int lanec = (tid & 31) * 4;    // column group (4 cols)
    const int rowBase = b * 64;

    if (tid < 64) colw_s[tid] = g_colw[rowBase + tid];
    __syncthreads();

    // load 8 float4 of h_n (rows warp*8..+8, cols lanec..+4) — kept in regs
    float4 h[8];
    const float* hn = g_hn + (size_t)rowBase * 128;
#pragma unroll
    for (int i = 0; i < 8; i++)
        h[i] = *(const float4*)(hn + (warp * 8 + i) * 128 + lanec);

    // m-partial: p[c] = sum_rows colw[row] * h[row][c]
    float4 p = make_float4(0.f, 0.f, 0.f, 0.f);
#pragma unroll
    for (int i = 0; i < 8; i++) {
        float w = colw_s[warp * 8 + i];
        p.x = fmaf(w, h[i].x, p.x); p.y = fmaf(w, h[i].y, p.y);
        p.z = fmaf(w, h[i].z, p.z); p.w = fmaf(w, h[i].w, p.w);
    }
    *(float4*)&part[warp][lanec] = p;
    __syncthreads();
    if (tid < 128) {
        float s = 0.f;
#pragma unroll
        for (int w = 0; w < 8; w++) s += part[w][tid];
        g_mpartT[tid][b] = s;
    }
    __threadfence();
    if (tid == 0) last = (atomicAdd(&g_cnt, 1u) == 255u);
    __syncthreads();

    if (last) {
        // compute m + mm ONCE
        if (tid < 128) {
            const float4* mp = (const float4*)g_mpartT[tid];
            float s = 0.f;
#pragma unroll 32
            for (int w = 0; w < 64; w++) {
                float4 v = __ldcg(mp + w);
                s += v.x + v.y + v.z + v.w;
            }
            ms[tid] = s;
        }
        __syncthreads();
        if (tid < 128) {
            float s = Wm_b2[tid];
            const float* row = Wm_w2 + tid * 128;
#pragma unroll 8
            for (int k = 0; k < 128; k++) s = fmaf(ms[k], __ldg(row + k), s);
            g_mm[tid] = s;
        }
        __threadfence();
        __syncthreads();
        if (tid == 0) *((volatile unsigned*)&g_flag) = 1u;
    }

    // all blocks wait for mm (short: skew + one GEMV)
    if (tid == 0) {
        volatile unsigned* f = &g_flag;
        while (*f == 0u) __nanosleep(256);
    }
    __syncthreads();
    __threadfence();
    if (tid < 128) mm_s[tid] = __ldcg(&g_mm[tid]);
    __syncthreads();

    // epilogue from registers: out = relu(h + mm)
    {
        float4* ob = (float4*)(out + (size_t)rowBase * 128);
#pragma unroll
        for (int i = 0; i < 8; i++) {
            float4 v = h[i];
            v.x = fmaxf(v.x + mm_s[lanec + 0], 0.f);
            v.y = fmaxf(v.y + mm_s[lanec + 1], 0.f);
            v.z = fmaxf(v.z + mm_s[lanec + 2], 0.f);
            v.w = fmaxf(v.w + mm_s[lanec + 3], 0.f);
            ob[(warp * 8 + i) * 32 + (tid & 31)] = v;
        }
    }

    // reset sync state for next graph replay (only after all waits passed)
    __syncthreads();
    if (tid == 0) {
        unsigned r = atomicAdd(&g_done, 1u);
        if (r == 255u) {
            g_cnt = 0u; g_flag = 0u;
            __threadfence();
            g_done = 0u;
        }
    }
}

// ---------------------------------------------------------------------------
extern "C" void kernel_launch(void* const* d_in, const int* in_sizes, int n_in,
                              void* d_out, int out_size) {
    const int*   x    = (const int*)d_in[0];
    const int*   ea   = (const int*)d_in[1];
    const float* bn   = (const float*)d_in[2];
    const float* aemb = (const float*)d_in[3];
    const float* bemb = (const float*)d_in[4];
    const float* Wi_w = (const float*)d_in[5];
    const float* Wi_b = (const float*)d_in[6];
    const float* Wm_w = (const float*)d_in[7];
    const float* Wm_b = (const float*)d_in[8];

    // Only the last layer (i = 2) affects the output.
    const float* Wi_w2 = Wi_w + 2 * 128 * 256;
    const float* Wi_b2 = Wi_b + 2 * 128;
    const float* Wm_w2 = Wm_w + 2 * 128 * 128;
    const float* Wm_b2 = Wm_b + 2 * 128;

    const int smem = (64 * 129 + 128 * 64) * (int)sizeof(float);  // 65,792 B
    static bool attr_set = false;
    if (!attr_set) {
        cudaFuncSetAttribute(k_fused, cudaFuncAttributeMaxDynamicSharedMemorySize, smem);
        attr_set = true;
    }

    k_fused<<<256, 256, smem>>>(bn, x, ea, aemb, bemb, Wi_w2, Wi_b2);
    k_tail<<<256, 256>>>(Wm_w2, Wm_b2, (float*)d_out);
}